// round 2
// baseline (speedup 1.0000x reference)
#include <cuda_runtime.h>
#include <math.h>

#define MAXN 2000000
#define MAXPART 8192

__device__ float g_e[MAXN];      // exp(beta*(1+cos)) per row
__device__ float g_w[MAXN];      // sharpened (pre-normalized) weights
__device__ float g_part1[MAXPART];
__device__ float g_part2[MAXPART];
__device__ float g_kq[128];
__device__ float g_knorm;
__device__ float g_Se;
__device__ float g_Sw;

// ---------------- kernel 0: key prep ----------------
__global__ void k_prep(const float* __restrict__ k) {
    int t = threadIdx.x;           // 128 threads
    float v = k[t] + 1e-16f;
    g_kq[t] = v;
    __shared__ float sm[128];
    sm[t] = v * v;
    __syncthreads();
    for (int s = 64; s; s >>= 1) {
        if (t < s) sm[t] += sm[t + s];
        __syncthreads();
    }
    if (t == 0) g_knorm = fmaxf(sqrtf(sm[0]), 1e-12f);
}

// ---------------- kernel 1: similarity + exp (the 1 GB pass) ----------------
// warp-per-row, 4 rows per warp iteration (MLP=4 on the 512B row loads,
// 4 interleaved shfl-reduce chains for ILP).
__global__ __launch_bounds__(256) void k_sim(const float* __restrict__ mem,
                                             int n,
                                             const float* __restrict__ beta_p) {
    const int lane   = threadIdx.x & 31;
    const int warp   = (blockIdx.x * blockDim.x + threadIdx.x) >> 5;
    const int nwarps = (gridDim.x * blockDim.x) >> 5;

    const float4 kv    = reinterpret_cast<const float4*>(g_kq)[lane];
    const float  beta  = *beta_p;
    const float  knorm = g_knorm;

    float acc = 0.0f;

    for (long long base = (long long)warp * 4; base < n; base += (long long)nwarps * 4) {
        float d0 = 0.f, d1 = 0.f, d2 = 0.f, d3 = 0.f;
        float s0 = 0.f, s1 = 0.f, s2 = 0.f, s3 = 0.f;

        // load 4 rows (independent -> 4 outstanding ld.128 per lane)
        {
            long long r = base;
            if (r < n) {
                float4 v = reinterpret_cast<const float4*>(mem + r * 128)[lane];
                float x0 = v.x + 1e-16f, x1 = v.y + 1e-16f, x2 = v.z + 1e-16f, x3 = v.w + 1e-16f;
                d0 = x0 * kv.x + x1 * kv.y + x2 * kv.z + x3 * kv.w;
                s0 = x0 * x0 + x1 * x1 + x2 * x2 + x3 * x3;
            }
            r = base + 1;
            if (r < n) {
                float4 v = reinterpret_cast<const float4*>(mem + r * 128)[lane];
                float x0 = v.x + 1e-16f, x1 = v.y + 1e-16f, x2 = v.z + 1e-16f, x3 = v.w + 1e-16f;
                d1 = x0 * kv.x + x1 * kv.y + x2 * kv.z + x3 * kv.w;
                s1 = x0 * x0 + x1 * x1 + x2 * x2 + x3 * x3;
            }
            r = base + 2;
            if (r < n) {
                float4 v = reinterpret_cast<const float4*>(mem + r * 128)[lane];
                float x0 = v.x + 1e-16f, x1 = v.y + 1e-16f, x2 = v.z + 1e-16f, x3 = v.w + 1e-16f;
                d2 = x0 * kv.x + x1 * kv.y + x2 * kv.z + x3 * kv.w;
                s2 = x0 * x0 + x1 * x1 + x2 * x2 + x3 * x3;
            }
            r = base + 3;
            if (r < n) {
                float4 v = reinterpret_cast<const float4*>(mem + r * 128)[lane];
                float x0 = v.x + 1e-16f, x1 = v.y + 1e-16f, x2 = v.z + 1e-16f, x3 = v.w + 1e-16f;
                d3 = x0 * kv.x + x1 * kv.y + x2 * kv.z + x3 * kv.w;
                s3 = x0 * x0 + x1 * x1 + x2 * x2 + x3 * x3;
            }
        }

        // butterfly reduce, 4 independent chains interleaved
        #pragma unroll
        for (int off = 16; off; off >>= 1) {
            d0 += __shfl_xor_sync(0xffffffffu, d0, off);
            d1 += __shfl_xor_sync(0xffffffffu, d1, off);
            d2 += __shfl_xor_sync(0xffffffffu, d2, off);
            d3 += __shfl_xor_sync(0xffffffffu, d3, off);
            s0 += __shfl_xor_sync(0xffffffffu, s0, off);
            s1 += __shfl_xor_sync(0xffffffffu, s1, off);
            s2 += __shfl_xor_sync(0xffffffffu, s2, off);
            s3 += __shfl_xor_sync(0xffffffffu, s3, off);
        }

        if (lane < 4) {
            long long r = base + lane;
            if (r < n) {
                float dd = (lane == 0) ? d0 : (lane == 1) ? d1 : (lane == 2) ? d2 : d3;
                float ss = (lane == 0) ? s0 : (lane == 1) ? s1 : (lane == 2) ? s2 : s3;
                float rn  = fmaxf(sqrtf(ss), 1e-12f);
                float cosv = dd / (rn * knorm);
                float e = expf(beta * (1.0f + cosv));
                g_e[r] = e;
                acc += e;
            }
        }
    }

    // block reduce acc -> g_part1[blockIdx.x]  (deterministic, no atomics)
    __shared__ float sm[256];
    sm[threadIdx.x] = acc;
    __syncthreads();
    for (int s = 128; s; s >>= 1) {
        if (threadIdx.x < s) sm[threadIdx.x] += sm[threadIdx.x + s];
        __syncthreads();
    }
    if (threadIdx.x == 0) g_part1[blockIdx.x] = sm[0];
}

// ---------------- deterministic partial-sum reduce ----------------
// which = 0: g_part1 -> g_Se ; which = 1: g_part2 -> g_Sw
__global__ void k_reduce(int which, int cnt) {
    const float* part = (which == 0) ? g_part1 : g_part2;
    __shared__ float sm[1024];
    float a = 0.f;
    for (int i = threadIdx.x; i < cnt; i += blockDim.x) a += part[i];
    sm[threadIdx.x] = a;
    __syncthreads();
    for (int s = 512; s; s >>= 1) {
        if (threadIdx.x < s) sm[threadIdx.x] += sm[threadIdx.x + s];
        __syncthreads();
    }
    if (threadIdx.x == 0) {
        if (which == 0) g_Se = sm[0];
        else            g_Sw = sm[0];
    }
}

// ---------------- kernel 3: interpolate + shift + sharpen ----------------
__global__ __launch_bounds__(256) void k_shift(const float* __restrict__ wp, int n,
                                               const float* __restrict__ g_p,
                                               const float* __restrict__ s_p,
                                               const float* __restrict__ gamma_p) {
    int i = blockIdx.x * blockDim.x + threadIdx.x;
    float part = 0.f;
    if (i < n) {
        float gg = *g_p;
        float s0 = s_p[0], s1 = s_p[1], s2 = s_p[2];
        float gamma = *gamma_p;
        float invSe = 1.0f / g_Se;
        float one_m_g = 1.0f - gg;

        int im1 = (i == 0) ? (n - 1) : (i - 1);
        int ip1 = (i == n - 1) ? 0 : (i + 1);

        float wgm = gg * g_e[im1] * invSe + one_m_g * wp[im1];
        float wgc = gg * g_e[i]   * invSe + one_m_g * wp[i];
        float wgp = gg * g_e[ip1] * invSe + one_m_g * wp[ip1];

        float wh = s0 * wgm + s1 * wgc + s2 * wgp;
        float w  = powf(wh, gamma);
        g_w[i] = w;
        part = w;
    }
    __shared__ float sm[256];
    sm[threadIdx.x] = part;
    __syncthreads();
    for (int s = 128; s; s >>= 1) {
        if (threadIdx.x < s) sm[threadIdx.x] += sm[threadIdx.x + s];
        __syncthreads();
    }
    if (threadIdx.x == 0) g_part2[blockIdx.x] = sm[0];
}

// ---------------- kernel 4: normalize ----------------
__global__ __launch_bounds__(256) void k_norm(float* __restrict__ out, int n) {
    int i = blockIdx.x * blockDim.x + threadIdx.x;
    if (i < n) {
        float inv = 1.0f / (g_Sw + 1e-16f);
        out[i] = g_w[i] * inv;
    }
}

extern "C" void kernel_launch(void* const* d_in, const int* in_sizes, int n_in,
                              void* d_out, int out_size) {
    // inputs: mem [N,128], k [128], beta [1], g [1], s [3], gamma [1], w_prev [N]
    const float* mem    = (const float*)d_in[0];
    const float* k      = (const float*)d_in[1];
    const float* beta_p = (const float*)d_in[2];
    const float* g_p    = (const float*)d_in[3];
    const float* s_p    = (const float*)d_in[4];
    const float* gamma_p= (const float*)d_in[5];
    const float* wp     = (const float*)d_in[6];
    float* out = (float*)d_out;

    int n = in_sizes[6];  // N rows

    const int G1 = 2048;                   // k_sim blocks (<= MAXPART)
    const int G3 = (n + 255) / 256;        // elementwise grids

    k_prep<<<1, 128>>>(k);
    k_sim<<<G1, 256>>>(mem, n, beta_p);
    k_reduce<<<1, 1024>>>(0, G1);
    k_shift<<<G3, 256>>>(wp, n, g_p, s_p, gamma_p);
    k_reduce<<<1, 1024>>>(1, G3);
    k_norm<<<G3, 256>>>(out, n);
}

// round 4
// speedup vs baseline: 1.6119x; 1.6119x over previous
#include <cuda_runtime.h>
#include <math.h>

#define MAXN 2000000
#define MAXPART 8192

__device__ float g_e[MAXN];      // exp(beta*(1+cos)) per row
__device__ float g_w[MAXN];      // sharpened (pre-normalized) weights
__device__ float g_part1[MAXPART];
__device__ float g_part2[MAXPART];
__device__ float g_kq[128];
__device__ float g_knorm;
__device__ float g_Se;
__device__ float g_Sw;

// ---------------- kernel 0: key prep ----------------
__global__ void k_prep(const float* __restrict__ k) {
    int t = threadIdx.x;           // 128 threads
    float v = k[t] + 1e-16f;
    g_kq[t] = v;
    __shared__ float sm[128];
    sm[t] = v * v;
    __syncthreads();
    for (int s = 64; s; s >>= 1) {
        if (t < s) sm[t] += sm[t + s];
        __syncthreads();
    }
    if (t == 0) g_knorm = fmaxf(sqrtf(sm[0]), 1e-12f);
}

// ---------------- kernel 1: similarity + exp (the 1 GB pass) ----------------
// warp-per-row, 4 rows per iteration, software-pipelined (prefetch next tile
// before reducing current) so loads stay outstanding during the shfl chains.
__global__ __launch_bounds__(256) void k_sim(const float* __restrict__ mem,
                                             int n,
                                             const float* __restrict__ beta_p) {
    const int lane   = threadIdx.x & 31;
    const int warp   = (blockIdx.x * blockDim.x + threadIdx.x) >> 5;
    const int nwarps = (gridDim.x * blockDim.x) >> 5;

    const float4 kv    = reinterpret_cast<const float4*>(g_kq)[lane];
    const float  beta  = *beta_p;
    const float  knorm = g_knorm;

    float acc = 0.0f;

    const long long stride = (long long)nwarps * 4;
    long long base = (long long)warp * 4;
    const long long nl = n;

    // clamped streaming load (rows beyond n read row n-1; results masked later)
    auto ldrow = [&](long long r) -> float4 {
        long long rr = r < nl ? r : (nl - 1);
        return __ldcs(reinterpret_cast<const float4*>(mem + rr * 128) + lane);
    };

    if (base < nl) {
        float4 c0 = ldrow(base);
        float4 c1 = ldrow(base + 1);
        float4 c2 = ldrow(base + 2);
        float4 c3 = ldrow(base + 3);

        while (true) {
            long long nxt = base + stride;
            float4 p0, p1, p2, p3;
            bool more = nxt < nl;
            if (more) {            // prefetch next tile (stays in flight during reduce)
                p0 = ldrow(nxt);
                p1 = ldrow(nxt + 1);
                p2 = ldrow(nxt + 2);
                p3 = ldrow(nxt + 3);
            }

            // per-lane partial dot & sumsq for 4 rows
            float d0 = c0.x * kv.x; d0 = fmaf(c0.y, kv.y, d0); d0 = fmaf(c0.z, kv.z, d0); d0 = fmaf(c0.w, kv.w, d0);
            float d1 = c1.x * kv.x; d1 = fmaf(c1.y, kv.y, d1); d1 = fmaf(c1.z, kv.z, d1); d1 = fmaf(c1.w, kv.w, d1);
            float d2 = c2.x * kv.x; d2 = fmaf(c2.y, kv.y, d2); d2 = fmaf(c2.z, kv.z, d2); d2 = fmaf(c2.w, kv.w, d2);
            float d3 = c3.x * kv.x; d3 = fmaf(c3.y, kv.y, d3); d3 = fmaf(c3.z, kv.z, d3); d3 = fmaf(c3.w, kv.w, d3);
            float s0 = c0.x * c0.x; s0 = fmaf(c0.y, c0.y, s0); s0 = fmaf(c0.z, c0.z, s0); s0 = fmaf(c0.w, c0.w, s0);
            float s1 = c1.x * c1.x; s1 = fmaf(c1.y, c1.y, s1); s1 = fmaf(c1.z, c1.z, s1); s1 = fmaf(c1.w, c1.w, s1);
            float s2 = c2.x * c2.x; s2 = fmaf(c2.y, c2.y, s2); s2 = fmaf(c2.z, c2.z, s2); s2 = fmaf(c2.w, c2.w, s2);
            float s3 = c3.x * c3.x; s3 = fmaf(c3.y, c3.y, s3); s3 = fmaf(c3.z, c3.z, s3); s3 = fmaf(c3.w, c3.w, s3);

            #pragma unroll
            for (int off = 16; off; off >>= 1) {
                d0 += __shfl_xor_sync(0xffffffffu, d0, off);
                d1 += __shfl_xor_sync(0xffffffffu, d1, off);
                d2 += __shfl_xor_sync(0xffffffffu, d2, off);
                d3 += __shfl_xor_sync(0xffffffffu, d3, off);
                s0 += __shfl_xor_sync(0xffffffffu, s0, off);
                s1 += __shfl_xor_sync(0xffffffffu, s1, off);
                s2 += __shfl_xor_sync(0xffffffffu, s2, off);
                s3 += __shfl_xor_sync(0xffffffffu, s3, off);
            }

            if (lane < 4) {
                long long r = base + lane;
                if (r < nl) {
                    float dd = (lane == 0) ? d0 : (lane == 1) ? d1 : (lane == 2) ? d2 : d3;
                    float ss = (lane == 0) ? s0 : (lane == 1) ? s1 : (lane == 2) ? s2 : s3;
                    float rn  = fmaxf(sqrtf(ss), 1e-12f);
                    float cosv = dd / (rn * knorm);
                    float e = expf(beta * (1.0f + cosv));
                    g_e[r] = e;
                    acc += e;
                }
            }

            if (!more) break;
            base = nxt;
            c0 = p0; c1 = p1; c2 = p2; c3 = p3;
        }
    }

    // block reduce acc -> g_part1[blockIdx.x]  (deterministic, no atomics)
    __shared__ float sm[256];
    sm[threadIdx.x] = acc;
    __syncthreads();
    for (int s = 128; s; s >>= 1) {
        if (threadIdx.x < s) sm[threadIdx.x] += sm[threadIdx.x + s];
        __syncthreads();
    }
    if (threadIdx.x == 0) g_part1[blockIdx.x] = sm[0];
}

// ---------------- deterministic partial-sum reduce ----------------
__global__ void k_reduce(int which, int cnt) {
    const float* part = (which == 0) ? g_part1 : g_part2;
    __shared__ float sm[1024];
    float a = 0.f;
    for (int i = threadIdx.x; i < cnt; i += blockDim.x) a += part[i];
    sm[threadIdx.x] = a;
    __syncthreads();
    for (int s = 512; s; s >>= 1) {
        if (threadIdx.x < s) sm[threadIdx.x] += sm[threadIdx.x + s];
        __syncthreads();
    }
    if (threadIdx.x == 0) {
        if (which == 0) g_Se = sm[0];
        else            g_Sw = sm[0];
    }
}

// ---------------- kernel 3: interpolate + shift + sharpen (grid-stride) ----------------
__global__ __launch_bounds__(256) void k_shift(const float* __restrict__ wp, int n,
                                               const float* __restrict__ g_p,
                                               const float* __restrict__ s_p,
                                               const float* __restrict__ gamma_p) {
    const float gg = *g_p;
    const float s0 = s_p[0], s1 = s_p[1], s2 = s_p[2];
    const float gamma = *gamma_p;
    const float invSe = 1.0f / g_Se;
    const float one_m_g = 1.0f - gg;
    const float gs = gg * invSe;

    float part = 0.f;
    int tid = blockIdx.x * blockDim.x + threadIdx.x;
    int ntot = gridDim.x * blockDim.x;
    for (int i = tid; i < n; i += ntot) {
        int im1 = (i == 0) ? (n - 1) : (i - 1);
        int ip1 = (i == n - 1) ? 0 : (i + 1);

        float wgm = fmaf(gs, g_e[im1], one_m_g * wp[im1]);
        float wgc = fmaf(gs, g_e[i],   one_m_g * wp[i]);
        float wgp = fmaf(gs, g_e[ip1], one_m_g * wp[ip1]);

        float wh = s0 * wgm; wh = fmaf(s1, wgc, wh); wh = fmaf(s2, wgp, wh);
        // wh > 0 guaranteed (g_e > 0, softmax s > 0); fast pow is plenty accurate
        float w = __powf(wh, gamma);
        g_w[i] = w;
        part += w;
    }
    __shared__ float sm[256];
    sm[threadIdx.x] = part;
    __syncthreads();
    for (int s = 128; s; s >>= 1) {
        if (threadIdx.x < s) sm[threadIdx.x] += sm[threadIdx.x + s];
        __syncthreads();
    }
    if (threadIdx.x == 0) g_part2[blockIdx.x] = sm[0];
}

// ---------------- kernel 4: normalize (vectorized) ----------------
__global__ __launch_bounds__(256) void k_norm4(float4* __restrict__ out, int n4) {
    int i = blockIdx.x * blockDim.x + threadIdx.x;
    if (i < n4) {
        float inv = 1.0f / (g_Sw + 1e-16f);
        float4 v = reinterpret_cast<const float4*>(g_w)[i];
        v.x *= inv; v.y *= inv; v.z *= inv; v.w *= inv;
        out[i] = v;
    }
}

__global__ __launch_bounds__(256) void k_norm1(float* __restrict__ out, int n) {
    int i = blockIdx.x * blockDim.x + threadIdx.x;
    if (i < n) {
        float inv = 1.0f / (g_Sw + 1e-16f);
        out[i] = g_w[i] * inv;
    }
}

extern "C" void kernel_launch(void* const* d_in, const int* in_sizes, int n_in,
                              void* d_out, int out_size) {
    // inputs: mem [N,128], k [128], beta [1], g [1], s [3], gamma [1], w_prev [N]
    const float* mem    = (const float*)d_in[0];
    const float* k      = (const float*)d_in[1];
    const float* beta_p = (const float*)d_in[2];
    const float* g_p    = (const float*)d_in[3];
    const float* s_p    = (const float*)d_in[4];
    const float* gamma_p= (const float*)d_in[5];
    const float* wp     = (const float*)d_in[6];
    float* out = (float*)d_out;

    int n = in_sizes[6];  // N rows

    const int G1 = 2048;   // k_sim blocks (grid-stride)
    const int G3 = 2048;   // k_shift blocks (grid-stride)

    k_prep<<<1, 128>>>(k);
    k_sim<<<G1, 256>>>(mem, n, beta_p);
    k_reduce<<<1, 1024>>>(0, G1);
    k_shift<<<G3, 256>>>(wp, n, g_p, s_p, gamma_p);
    k_reduce<<<1, 1024>>>(1, G3);
    if ((n & 3) == 0) {
        int n4 = n >> 2;
        k_norm4<<<(n4 + 255) / 256, 256>>>((float4*)out, n4);
    } else {
        k_norm1<<<(n + 255) / 256, 256>>>(out, n);
    }
}

// round 6
// speedup vs baseline: 1.6604x; 1.0301x over previous
#include <cuda_runtime.h>
#include <math.h>

#define MAXN 2000000
#define MAXPART 8192

__device__ float g_e[MAXN];      // exp(beta*(1+cos)) per row
__device__ float g_w[MAXN];      // sharpened (pre-normalized) weights
__device__ float g_part1[MAXPART];
__device__ float g_part2[MAXPART];
__device__ float g_Se;
__device__ float g_Sw;

// ---------------- kernel 1: similarity + exp (the 1 GB pass) ----------------
// warp-per-row, 4 rows per iteration, software-pipelined. Key prep is done
// per-warp inline (k is 512B, L2-resident) — no separate prep kernel.
__global__ __launch_bounds__(256) void k_sim(const float* __restrict__ mem,
                                             int n,
                                             const float* __restrict__ kvec,
                                             const float* __restrict__ beta_p) {
    const int lane   = threadIdx.x & 31;
    const int warp   = (blockIdx.x * blockDim.x + threadIdx.x) >> 5;
    const int nwarps = (gridDim.x * blockDim.x) >> 5;

    // inline key prep: kq = k + 1e-16, knorm = ||kq||
    float4 kv = reinterpret_cast<const float4*>(kvec)[lane];
    kv.x += 1e-16f; kv.y += 1e-16f; kv.z += 1e-16f; kv.w += 1e-16f;
    float kk = kv.x * kv.x;
    kk = fmaf(kv.y, kv.y, kk); kk = fmaf(kv.z, kv.z, kk); kk = fmaf(kv.w, kv.w, kk);
    #pragma unroll
    for (int off = 16; off; off >>= 1) kk += __shfl_xor_sync(0xffffffffu, kk, off);
    const float knorm = fmaxf(sqrtf(kk), 1e-12f);
    const float beta  = *beta_p;

    float acc = 0.0f;

    const long long stride = (long long)nwarps * 4;
    long long base = (long long)warp * 4;
    const long long nl = n;

    // clamped streaming load (rows beyond n read row n-1; results masked later)
    auto ldrow = [&](long long r) -> float4 {
        long long rr = r < nl ? r : (nl - 1);
        return __ldcs(reinterpret_cast<const float4*>(mem + rr * 128) + lane);
    };

    if (base < nl) {
        float4 c0 = ldrow(base);
        float4 c1 = ldrow(base + 1);
        float4 c2 = ldrow(base + 2);
        float4 c3 = ldrow(base + 3);

        while (true) {
            long long nxt = base + stride;
            float4 p0, p1, p2, p3;
            bool more = nxt < nl;
            if (more) {            // prefetch next tile (stays in flight during reduce)
                p0 = ldrow(nxt);
                p1 = ldrow(nxt + 1);
                p2 = ldrow(nxt + 2);
                p3 = ldrow(nxt + 3);
            }

            float d0 = c0.x * kv.x; d0 = fmaf(c0.y, kv.y, d0); d0 = fmaf(c0.z, kv.z, d0); d0 = fmaf(c0.w, kv.w, d0);
            float d1 = c1.x * kv.x; d1 = fmaf(c1.y, kv.y, d1); d1 = fmaf(c1.z, kv.z, d1); d1 = fmaf(c1.w, kv.w, d1);
            float d2 = c2.x * kv.x; d2 = fmaf(c2.y, kv.y, d2); d2 = fmaf(c2.z, kv.z, d2); d2 = fmaf(c2.w, kv.w, d2);
            float d3 = c3.x * kv.x; d3 = fmaf(c3.y, kv.y, d3); d3 = fmaf(c3.z, kv.z, d3); d3 = fmaf(c3.w, kv.w, d3);
            float s0 = c0.x * c0.x; s0 = fmaf(c0.y, c0.y, s0); s0 = fmaf(c0.z, c0.z, s0); s0 = fmaf(c0.w, c0.w, s0);
            float s1 = c1.x * c1.x; s1 = fmaf(c1.y, c1.y, s1); s1 = fmaf(c1.z, c1.z, s1); s1 = fmaf(c1.w, c1.w, s1);
            float s2 = c2.x * c2.x; s2 = fmaf(c2.y, c2.y, s2); s2 = fmaf(c2.z, c2.z, s2); s2 = fmaf(c2.w, c2.w, s2);
            float s3 = c3.x * c3.x; s3 = fmaf(c3.y, c3.y, s3); s3 = fmaf(c3.z, c3.z, s3); s3 = fmaf(c3.w, c3.w, s3);

            #pragma unroll
            for (int off = 16; off; off >>= 1) {
                d0 += __shfl_xor_sync(0xffffffffu, d0, off);
                d1 += __shfl_xor_sync(0xffffffffu, d1, off);
                d2 += __shfl_xor_sync(0xffffffffu, d2, off);
                d3 += __shfl_xor_sync(0xffffffffu, d3, off);
                s0 += __shfl_xor_sync(0xffffffffu, s0, off);
                s1 += __shfl_xor_sync(0xffffffffu, s1, off);
                s2 += __shfl_xor_sync(0xffffffffu, s2, off);
                s3 += __shfl_xor_sync(0xffffffffu, s3, off);
            }

            if (lane < 4) {
                long long r = base + lane;
                if (r < nl) {
                    float dd = (lane == 0) ? d0 : (lane == 1) ? d1 : (lane == 2) ? d2 : d3;
                    float ss = (lane == 0) ? s0 : (lane == 1) ? s1 : (lane == 2) ? s2 : s3;
                    float rn  = fmaxf(sqrtf(ss), 1e-12f);
                    float cosv = dd / (rn * knorm);
                    float e = expf(beta * (1.0f + cosv));
                    g_e[r] = e;
                    acc += e;
                }
            }

            if (!more) break;
            base = nxt;
            c0 = p0; c1 = p1; c2 = p2; c3 = p3;
        }
    }

    __shared__ float sm[256];
    sm[threadIdx.x] = acc;
    __syncthreads();
    for (int s = 128; s; s >>= 1) {
        if (threadIdx.x < s) sm[threadIdx.x] += sm[threadIdx.x + s];
        __syncthreads();
    }
    if (threadIdx.x == 0) g_part1[blockIdx.x] = sm[0];
}

// ---------------- deterministic partial-sum reduce ----------------
__global__ void k_reduce(int which, int cnt) {
    const float* part = (which == 0) ? g_part1 : g_part2;
    __shared__ float sm[1024];
    float a = 0.f;
    for (int i = threadIdx.x; i < cnt; i += blockDim.x) a += part[i];
    sm[threadIdx.x] = a;
    __syncthreads();
    for (int s = 512; s; s >>= 1) {
        if (threadIdx.x < s) sm[threadIdx.x] += sm[threadIdx.x + s];
        __syncthreads();
    }
    if (threadIdx.x == 0) {
        if (which == 0) g_Se = sm[0];
        else            g_Sw = sm[0];
    }
}

// ---------------- kernel 3: interpolate + shift + sharpen, 4-wide ----------------
// thread handles elements [4i, 4i+3]; needs e/wp at [4i-1, 4i+4]:
// one float4 + two halo scalars per array.
__global__ __launch_bounds__(256) void k_shift4(const float* __restrict__ wp, int n4, int n,
                                                const float* __restrict__ g_p,
                                                const float* __restrict__ s_p,
                                                const float* __restrict__ gamma_p) {
    const float gg = *g_p;
    const float s0 = s_p[0], s1 = s_p[1], s2 = s_p[2];
    const float gamma = *gamma_p;
    const float one_m_g = 1.0f - gg;
    const float gs = gg / g_Se;

    float part = 0.f;
    int i = blockIdx.x * blockDim.x + threadIdx.x;
    if (i < n4) {
        int j = i << 2;
        int jm1 = (j == 0) ? (n - 1) : (j - 1);
        int jp4 = (j + 4 == n) ? 0 : (j + 4);

        float4 E  = reinterpret_cast<const float4*>(g_e)[i];
        float4 W  = reinterpret_cast<const float4*>(wp)[i];
        float em1 = g_e[jm1], ep4 = g_e[jp4];
        float wm1 = wp[jm1],  wp4 = wp[jp4];

        // wg at positions j-1 .. j+4
        float a0 = fmaf(gs, em1, one_m_g * wm1);
        float a1 = fmaf(gs, E.x, one_m_g * W.x);
        float a2 = fmaf(gs, E.y, one_m_g * W.y);
        float a3 = fmaf(gs, E.z, one_m_g * W.z);
        float a4 = fmaf(gs, E.w, one_m_g * W.w);
        float a5 = fmaf(gs, ep4, one_m_g * wp4);

        float h0 = s0 * a0; h0 = fmaf(s1, a1, h0); h0 = fmaf(s2, a2, h0);
        float h1 = s0 * a1; h1 = fmaf(s1, a2, h1); h1 = fmaf(s2, a3, h1);
        float h2 = s0 * a2; h2 = fmaf(s1, a3, h2); h2 = fmaf(s2, a4, h2);
        float h3 = s0 * a3; h3 = fmaf(s1, a4, h3); h3 = fmaf(s2, a5, h3);

        float4 o;
        o.x = __powf(h0, gamma);
        o.y = __powf(h1, gamma);
        o.z = __powf(h2, gamma);
        o.w = __powf(h3, gamma);
        reinterpret_cast<float4*>(g_w)[i] = o;
        part = (o.x + o.y) + (o.z + o.w);
    }
    __shared__ float sm[256];
    sm[threadIdx.x] = part;
    __syncthreads();
    for (int s = 128; s; s >>= 1) {
        if (threadIdx.x < s) sm[threadIdx.x] += sm[threadIdx.x + s];
        __syncthreads();
    }
    if (threadIdx.x == 0) g_part2[blockIdx.x] = sm[0];
}

// scalar fallback (n not divisible by 4)
__global__ __launch_bounds__(256) void k_shift1(const float* __restrict__ wp, int n,
                                                const float* __restrict__ g_p,
                                                const float* __restrict__ s_p,
                                                const float* __restrict__ gamma_p) {
    const float gg = *g_p;
    const float s0 = s_p[0], s1 = s_p[1], s2 = s_p[2];
    const float gamma = *gamma_p;
    const float one_m_g = 1.0f - gg;
    const float gs = gg / g_Se;

    float part = 0.f;
    int tid = blockIdx.x * blockDim.x + threadIdx.x;
    int ntot = gridDim.x * blockDim.x;
    for (int i = tid; i < n; i += ntot) {
        int im1 = (i == 0) ? (n - 1) : (i - 1);
        int ip1 = (i == n - 1) ? 0 : (i + 1);
        float wgm = fmaf(gs, g_e[im1], one_m_g * wp[im1]);
        float wgc = fmaf(gs, g_e[i],   one_m_g * wp[i]);
        float wgp = fmaf(gs, g_e[ip1], one_m_g * wp[ip1]);
        float wh = s0 * wgm; wh = fmaf(s1, wgc, wh); wh = fmaf(s2, wgp, wh);
        float w = __powf(wh, gamma);
        g_w[i] = w;
        part += w;
    }
    __shared__ float sm[256];
    sm[threadIdx.x] = part;
    __syncthreads();
    for (int s = 128; s; s >>= 1) {
        if (threadIdx.x < s) sm[threadIdx.x] += sm[threadIdx.x + s];
        __syncthreads();
    }
    if (threadIdx.x == 0) g_part2[blockIdx.x] = sm[0];
}

// ---------------- kernel 4: normalize ----------------
__global__ __launch_bounds__(256) void k_norm4(float4* __restrict__ out, int n4) {
    int i = blockIdx.x * blockDim.x + threadIdx.x;
    if (i < n4) {
        float inv = 1.0f / (g_Sw + 1e-16f);
        float4 v = reinterpret_cast<const float4*>(g_w)[i];
        v.x *= inv; v.y *= inv; v.z *= inv; v.w *= inv;
        out[i] = v;
    }
}

__global__ __launch_bounds__(256) void k_norm1(float* __restrict__ out, int n) {
    int i = blockIdx.x * blockDim.x + threadIdx.x;
    if (i < n) {
        float inv = 1.0f / (g_Sw + 1e-16f);
        out[i] = g_w[i] * inv;
    }
}

extern "C" void kernel_launch(void* const* d_in, const int* in_sizes, int n_in,
                              void* d_out, int out_size) {
    // inputs: mem [N,128], k [128], beta [1], g [1], s [3], gamma [1], w_prev [N]
    const float* mem    = (const float*)d_in[0];
    const float* k      = (const float*)d_in[1];
    const float* beta_p = (const float*)d_in[2];
    const float* g_p    = (const float*)d_in[3];
    const float* s_p    = (const float*)d_in[4];
    const float* gamma_p= (const float*)d_in[5];
    const float* wp     = (const float*)d_in[6];
    float* out = (float*)d_out;

    int n = in_sizes[6];  // N rows

    const int G1 = 2048;   // k_sim blocks (grid-stride)

    k_sim<<<G1, 256>>>(mem, n, k, beta_p);
    k_reduce<<<1, 1024>>>(0, G1);

    if ((n & 3) == 0) {
        int n4 = n >> 2;
        int G3 = (n4 + 255) / 256;   // 1954 for n=2e6, fits MAXPART
        k_shift4<<<G3, 256>>>(wp, n4, n, g_p, s_p, gamma_p);
        k_reduce<<<1, 1024>>>(1, G3);
        k_norm4<<<(n4 + 255) / 256, 256>>>((float4*)out, n4);
    } else {
        int G3 = 2048;
        k_shift1<<<G3, 256>>>(wp, n, g_p, s_p, gamma_p);
        k_reduce<<<1, 1024>>>(1, G3);
        k_norm1<<<(n + 255) / 256, 256>>>(out, n);
    }
}

// round 7
// speedup vs baseline: 1.6709x; 1.0063x over previous
#include <cuda_runtime.h>
#include <math.h>

#define MAXN 2000000
#define MAXPART 8192

__device__ float g_e[MAXN];      // exp(beta*(1+cos)) per row
__device__ float g_w[MAXN];      // sharpened (pre-normalized) weights
__device__ float g_part1[MAXPART];
__device__ float g_part2[MAXPART];

// ---------------- kernel 1: similarity + exp (the 1 GB pass) ----------------
// warp-per-row, 4 rows per iteration, software-pipelined. Key prep inline.
__global__ __launch_bounds__(256) void k_sim(const float* __restrict__ mem,
                                             int n,
                                             const float* __restrict__ kvec,
                                             const float* __restrict__ beta_p) {
    const int lane   = threadIdx.x & 31;
    const int warp   = (blockIdx.x * blockDim.x + threadIdx.x) >> 5;
    const int nwarps = (gridDim.x * blockDim.x) >> 5;

    // inline key prep: kq = k + 1e-16, knorm = ||kq||
    float4 kv = reinterpret_cast<const float4*>(kvec)[lane];
    kv.x += 1e-16f; kv.y += 1e-16f; kv.z += 1e-16f; kv.w += 1e-16f;
    float kk = kv.x * kv.x;
    kk = fmaf(kv.y, kv.y, kk); kk = fmaf(kv.z, kv.z, kk); kk = fmaf(kv.w, kv.w, kk);
    #pragma unroll
    for (int off = 16; off; off >>= 1) kk += __shfl_xor_sync(0xffffffffu, kk, off);
    const float knorm = fmaxf(sqrtf(kk), 1e-12f);
    const float beta  = *beta_p;

    float acc = 0.0f;

    const long long stride = (long long)nwarps * 4;
    long long base = (long long)warp * 4;
    const long long nl = n;

    auto ldrow = [&](long long r) -> float4 {
        long long rr = r < nl ? r : (nl - 1);
        return __ldcs(reinterpret_cast<const float4*>(mem + rr * 128) + lane);
    };

    if (base < nl) {
        float4 c0 = ldrow(base);
        float4 c1 = ldrow(base + 1);
        float4 c2 = ldrow(base + 2);
        float4 c3 = ldrow(base + 3);

        while (true) {
            long long nxt = base + stride;
            float4 p0, p1, p2, p3;
            bool more = nxt < nl;
            if (more) {            // prefetch next tile (stays in flight during reduce)
                p0 = ldrow(nxt);
                p1 = ldrow(nxt + 1);
                p2 = ldrow(nxt + 2);
                p3 = ldrow(nxt + 3);
            }

            float d0 = c0.x * kv.x; d0 = fmaf(c0.y, kv.y, d0); d0 = fmaf(c0.z, kv.z, d0); d0 = fmaf(c0.w, kv.w, d0);
            float d1 = c1.x * kv.x; d1 = fmaf(c1.y, kv.y, d1); d1 = fmaf(c1.z, kv.z, d1); d1 = fmaf(c1.w, kv.w, d1);
            float d2 = c2.x * kv.x; d2 = fmaf(c2.y, kv.y, d2); d2 = fmaf(c2.z, kv.z, d2); d2 = fmaf(c2.w, kv.w, d2);
            float d3 = c3.x * kv.x; d3 = fmaf(c3.y, kv.y, d3); d3 = fmaf(c3.z, kv.z, d3); d3 = fmaf(c3.w, kv.w, d3);
            float s0 = c0.x * c0.x; s0 = fmaf(c0.y, c0.y, s0); s0 = fmaf(c0.z, c0.z, s0); s0 = fmaf(c0.w, c0.w, s0);
            float s1 = c1.x * c1.x; s1 = fmaf(c1.y, c1.y, s1); s1 = fmaf(c1.z, c1.z, s1); s1 = fmaf(c1.w, c1.w, s1);
            float s2 = c2.x * c2.x; s2 = fmaf(c2.y, c2.y, s2); s2 = fmaf(c2.z, c2.z, s2); s2 = fmaf(c2.w, c2.w, s2);
            float s3 = c3.x * c3.x; s3 = fmaf(c3.y, c3.y, s3); s3 = fmaf(c3.z, c3.z, s3); s3 = fmaf(c3.w, c3.w, s3);

            #pragma unroll
            for (int off = 16; off; off >>= 1) {
                d0 += __shfl_xor_sync(0xffffffffu, d0, off);
                d1 += __shfl_xor_sync(0xffffffffu, d1, off);
                d2 += __shfl_xor_sync(0xffffffffu, d2, off);
                d3 += __shfl_xor_sync(0xffffffffu, d3, off);
                s0 += __shfl_xor_sync(0xffffffffu, s0, off);
                s1 += __shfl_xor_sync(0xffffffffu, s1, off);
                s2 += __shfl_xor_sync(0xffffffffu, s2, off);
                s3 += __shfl_xor_sync(0xffffffffu, s3, off);
            }

            if (lane < 4) {
                long long r = base + lane;
                if (r < nl) {
                    float dd = (lane == 0) ? d0 : (lane == 1) ? d1 : (lane == 2) ? d2 : d3;
                    float ss = (lane == 0) ? s0 : (lane == 1) ? s1 : (lane == 2) ? s2 : s3;
                    float rn  = fmaxf(sqrtf(ss), 1e-12f);
                    float cosv = dd / (rn * knorm);
                    float e = expf(beta * (1.0f + cosv));
                    g_e[r] = e;
                    acc += e;
                }
            }

            if (!more) break;
            base = nxt;
            c0 = p0; c1 = p1; c2 = p2; c3 = p3;
        }
    }

    __shared__ float sm[256];
    sm[threadIdx.x] = acc;
    __syncthreads();
    for (int s = 128; s; s >>= 1) {
        if (threadIdx.x < s) sm[threadIdx.x] += sm[threadIdx.x + s];
        __syncthreads();
    }
    if (threadIdx.x == 0) g_part1[blockIdx.x] = sm[0];
}

// ---- block-wide deterministic sum of a partials array (same result in every block) ----
__device__ __forceinline__ float block_sum_partials(const float* __restrict__ part, int cnt,
                                                    float* __restrict__ sm /*256 floats*/) {
    float a = 0.f;
    for (int i = threadIdx.x; i < cnt; i += 256) a += part[i];
    sm[threadIdx.x] = a;
    __syncthreads();
    #pragma unroll
    for (int s = 128; s; s >>= 1) {
        if (threadIdx.x < s) sm[threadIdx.x] += sm[threadIdx.x + s];
        __syncthreads();
    }
    float r = sm[0];
    __syncthreads();   // protect sm for reuse
    return r;
}

// ---------------- kernel 2: interpolate + shift + sharpen, 4-wide ----------------
// Preamble: every block reduces g_part1 -> Se (L2-resident, deterministic).
__global__ __launch_bounds__(256) void k_shift4(const float* __restrict__ wp, int n4, int n,
                                                int cnt1,
                                                const float* __restrict__ g_p,
                                                const float* __restrict__ s_p,
                                                const float* __restrict__ gamma_p) {
    __shared__ float sm[256];
    const float Se = block_sum_partials(g_part1, cnt1, sm);

    const float gg = *g_p;
    const float s0 = s_p[0], s1 = s_p[1], s2 = s_p[2];
    const float gamma = *gamma_p;
    const float one_m_g = 1.0f - gg;
    const float gs = gg / Se;

    float part = 0.f;
    int i = blockIdx.x * blockDim.x + threadIdx.x;
    if (i < n4) {
        int j = i << 2;
        int jm1 = (j == 0) ? (n - 1) : (j - 1);
        int jp4 = (j + 4 == n) ? 0 : (j + 4);

        float4 E  = reinterpret_cast<const float4*>(g_e)[i];
        float4 W  = reinterpret_cast<const float4*>(wp)[i];
        float em1 = g_e[jm1], ep4 = g_e[jp4];
        float wm1 = wp[jm1],  wp4 = wp[jp4];

        float a0 = fmaf(gs, em1, one_m_g * wm1);
        float a1 = fmaf(gs, E.x, one_m_g * W.x);
        float a2 = fmaf(gs, E.y, one_m_g * W.y);
        float a3 = fmaf(gs, E.z, one_m_g * W.z);
        float a4 = fmaf(gs, E.w, one_m_g * W.w);
        float a5 = fmaf(gs, ep4, one_m_g * wp4);

        float h0 = s0 * a0; h0 = fmaf(s1, a1, h0); h0 = fmaf(s2, a2, h0);
        float h1 = s0 * a1; h1 = fmaf(s1, a2, h1); h1 = fmaf(s2, a3, h1);
        float h2 = s0 * a2; h2 = fmaf(s1, a3, h2); h2 = fmaf(s2, a4, h2);
        float h3 = s0 * a3; h3 = fmaf(s1, a4, h3); h3 = fmaf(s2, a5, h3);

        float4 o;
        o.x = __powf(h0, gamma);
        o.y = __powf(h1, gamma);
        o.z = __powf(h2, gamma);
        o.w = __powf(h3, gamma);
        reinterpret_cast<float4*>(g_w)[i] = o;
        part = (o.x + o.y) + (o.z + o.w);
    }
    sm[threadIdx.x] = part;
    __syncthreads();
    for (int s = 128; s; s >>= 1) {
        if (threadIdx.x < s) sm[threadIdx.x] += sm[threadIdx.x + s];
        __syncthreads();
    }
    if (threadIdx.x == 0) g_part2[blockIdx.x] = sm[0];
}

// scalar fallback (n not divisible by 4)
__global__ __launch_bounds__(256) void k_shift1(const float* __restrict__ wp, int n,
                                                int cnt1,
                                                const float* __restrict__ g_p,
                                                const float* __restrict__ s_p,
                                                const float* __restrict__ gamma_p) {
    __shared__ float sm[256];
    const float Se = block_sum_partials(g_part1, cnt1, sm);

    const float gg = *g_p;
    const float s0 = s_p[0], s1 = s_p[1], s2 = s_p[2];
    const float gamma = *gamma_p;
    const float one_m_g = 1.0f - gg;
    const float gs = gg / Se;

    float part = 0.f;
    int tid = blockIdx.x * blockDim.x + threadIdx.x;
    int ntot = gridDim.x * blockDim.x;
    for (int i = tid; i < n; i += ntot) {
        int im1 = (i == 0) ? (n - 1) : (i - 1);
        int ip1 = (i == n - 1) ? 0 : (i + 1);
        float wgm = fmaf(gs, g_e[im1], one_m_g * wp[im1]);
        float wgc = fmaf(gs, g_e[i],   one_m_g * wp[i]);
        float wgp = fmaf(gs, g_e[ip1], one_m_g * wp[ip1]);
        float wh = s0 * wgm; wh = fmaf(s1, wgc, wh); wh = fmaf(s2, wgp, wh);
        float w = __powf(wh, gamma);
        g_w[i] = w;
        part += w;
    }
    sm[threadIdx.x] = part;
    __syncthreads();
    for (int s = 128; s; s >>= 1) {
        if (threadIdx.x < s) sm[threadIdx.x] += sm[threadIdx.x + s];
        __syncthreads();
    }
    if (threadIdx.x == 0) g_part2[blockIdx.x] = sm[0];
}

// ---------------- kernel 3: normalize (preamble reduces g_part2 -> Sw) ----------------
__global__ __launch_bounds__(256) void k_norm4(float4* __restrict__ out, int n4, int cnt2) {
    __shared__ float sm[256];
    const float Sw = block_sum_partials(g_part2, cnt2, sm);
    const float inv = 1.0f / (Sw + 1e-16f);

    int i = blockIdx.x * blockDim.x + threadIdx.x;
    if (i < n4) {
        float4 v = reinterpret_cast<const float4*>(g_w)[i];
        v.x *= inv; v.y *= inv; v.z *= inv; v.w *= inv;
        out[i] = v;
    }
}

__global__ __launch_bounds__(256) void k_norm1(float* __restrict__ out, int n, int cnt2) {
    __shared__ float sm[256];
    const float Sw = block_sum_partials(g_part2, cnt2, sm);
    const float inv = 1.0f / (Sw + 1e-16f);

    int i = blockIdx.x * blockDim.x + threadIdx.x;
    if (i < n) out[i] = g_w[i] * inv;
}

extern "C" void kernel_launch(void* const* d_in, const int* in_sizes, int n_in,
                              void* d_out, int out_size) {
    // inputs: mem [N,128], k [128], beta [1], g [1], s [3], gamma [1], w_prev [N]
    const float* mem    = (const float*)d_in[0];
    const float* k      = (const float*)d_in[1];
    const float* beta_p = (const float*)d_in[2];
    const float* g_p    = (const float*)d_in[3];
    const float* s_p    = (const float*)d_in[4];
    const float* gamma_p= (const float*)d_in[5];
    const float* wp     = (const float*)d_in[6];
    float* out = (float*)d_out;

    int n = in_sizes[6];  // N rows

    const int G1 = 2048;   // k_sim blocks (grid-stride)

    k_sim<<<G1, 256>>>(mem, n, k, beta_p);

    if ((n & 3) == 0) {
        int n4 = n >> 2;
        int G3 = (n4 + 255) / 256;   // 1954 for n=2e6
        k_shift4<<<G3, 256>>>(wp, n4, n, G1, g_p, s_p, gamma_p);
        k_norm4<<<G3, 256>>>((float4*)out, n4, G3);
    } else {
        int G3 = 2048;
        k_shift1<<<G3, 256>>>(wp, n, G1, g_p, s_p, gamma_p);
        k_norm1<<<(n + 255) / 256, 256>>>(out, n, G3);
    }
}

// round 8
// speedup vs baseline: 1.7492x; 1.0469x over previous
#include <cuda_runtime.h>
#include <math.h>

#define MAXN 2000000
#define MAXPART 8192

__device__ float g_e[MAXN];      // exp(beta*(1+cos)) per row
__device__ float g_w[MAXN];      // sharpened (pre-normalized) weights
__device__ float g_part1[MAXPART];
__device__ float g_part2[MAXPART];

// merge two butterfly chains at 'off': lanes with (lane&off)==0 continue chain a,
// others continue chain b. 2 shfls per merge.
__device__ __forceinline__ float merge2(float a, float b, int off, int lane) {
    float ta = __shfl_xor_sync(0xffffffffu, a, off);
    float tb = __shfl_xor_sync(0xffffffffu, b, off);
    return (lane & off) ? (b + tb) : (a + ta);
}

// ---------------- kernel 1: similarity + exp (the 1 GB pass) ----------------
// warp-per-row, 4 rows/iter, software-pipelined, merge-tree warp reduction.
// Launched with exactly one resident wave (148*4 blocks) for perfect balance.
__global__ __launch_bounds__(256) void k_sim(const float* __restrict__ mem,
                                             int n,
                                             const float* __restrict__ kvec,
                                             const float* __restrict__ beta_p) {
    const int lane   = threadIdx.x & 31;
    const int warp   = (blockIdx.x * blockDim.x + threadIdx.x) >> 5;
    const int nwarps = (gridDim.x * blockDim.x) >> 5;

    // inline key prep: kq = k + 1e-16, knorm = ||kq||
    float4 kv = reinterpret_cast<const float4*>(kvec)[lane];
    kv.x += 1e-16f; kv.y += 1e-16f; kv.z += 1e-16f; kv.w += 1e-16f;
    float kk = kv.x * kv.x;
    kk = fmaf(kv.y, kv.y, kk); kk = fmaf(kv.z, kv.z, kk); kk = fmaf(kv.w, kv.w, kk);
    #pragma unroll
    for (int off = 16; off; off >>= 1) kk += __shfl_xor_sync(0xffffffffu, kk, off);
    const float invknorm = 1.0f / fmaxf(sqrtf(kk), 1e-12f);
    const float beta  = *beta_p;

    // this lane's row (if compute lane): lanes 0,8,16,24 handle rows 0,2,1,3
    const bool is_cl  = ((lane & 7) == 0);
    const int  myrow  = ((lane >> 3) & 1) * 2 + ((lane >> 4) & 1);

    float acc = 0.0f;

    const long long stride = (long long)nwarps * 4;
    long long base = (long long)warp * 4;
    const long long nl = n;

    auto ldrow = [&](long long r) -> float4 {
        long long rr = r < nl ? r : (nl - 1);
        return __ldcs(reinterpret_cast<const float4*>(mem + rr * 128) + lane);
    };

    if (base < nl) {
        float4 c0 = ldrow(base);
        float4 c1 = ldrow(base + 1);
        float4 c2 = ldrow(base + 2);
        float4 c3 = ldrow(base + 3);

        while (true) {
            long long nxt = base + stride;
            float4 p0, p1, p2, p3;
            bool more = nxt < nl;
            if (more) {            // prefetch next tile (in flight during reduce)
                p0 = ldrow(nxt);
                p1 = ldrow(nxt + 1);
                p2 = ldrow(nxt + 2);
                p3 = ldrow(nxt + 3);
            }

            float d0 = c0.x * kv.x; d0 = fmaf(c0.y, kv.y, d0); d0 = fmaf(c0.z, kv.z, d0); d0 = fmaf(c0.w, kv.w, d0);
            float d1 = c1.x * kv.x; d1 = fmaf(c1.y, kv.y, d1); d1 = fmaf(c1.z, kv.z, d1); d1 = fmaf(c1.w, kv.w, d1);
            float d2 = c2.x * kv.x; d2 = fmaf(c2.y, kv.y, d2); d2 = fmaf(c2.z, kv.z, d2); d2 = fmaf(c2.w, kv.w, d2);
            float d3 = c3.x * kv.x; d3 = fmaf(c3.y, kv.y, d3); d3 = fmaf(c3.z, kv.z, d3); d3 = fmaf(c3.w, kv.w, d3);
            float s0 = c0.x * c0.x; s0 = fmaf(c0.y, c0.y, s0); s0 = fmaf(c0.z, c0.z, s0); s0 = fmaf(c0.w, c0.w, s0);
            float s1 = c1.x * c1.x; s1 = fmaf(c1.y, c1.y, s1); s1 = fmaf(c1.z, c1.z, s1); s1 = fmaf(c1.w, c1.w, s1);
            float s2 = c2.x * c2.x; s2 = fmaf(c2.y, c2.y, s2); s2 = fmaf(c2.z, c2.z, s2); s2 = fmaf(c2.w, c2.w, s2);
            float s3 = c3.x * c3.x; s3 = fmaf(c3.y, c3.y, s3); s3 = fmaf(c3.z, c3.z, s3); s3 = fmaf(c3.w, c3.w, s3);

            // merge-tree reduction: 8 chains -> 1 value/lane in 16 shfls.
            // level 16: (d0,d1) (d2,d3) (s0,s1) (s2,s3)
            float m0 = merge2(d0, d1, 16, lane);
            float m1 = merge2(d2, d3, 16, lane);
            float m2 = merge2(s0, s1, 16, lane);
            float m3 = merge2(s2, s3, 16, lane);
            // level 8: (m0,m1) (m2,m3)
            float n0 = merge2(m0, m1, 8, lane);
            float n1 = merge2(m2, m3, 8, lane);
            // level 4: (d-family, s-family)
            float q = merge2(n0, n1, 4, lane);
            // finish within remaining lanes
            q += __shfl_xor_sync(0xffffffffu, q, 2);
            q += __shfl_xor_sync(0xffffffffu, q, 1);
            // lane L: family=bit2 (0=dot,1=sumsq), row=2*bit3+bit4.
            // bring sumsq onto the dot lane:
            float qs = __shfl_xor_sync(0xffffffffu, q, 4);

            if (is_cl) {
                long long r = base + myrow;
                if (r < nl) {
                    float cosv = q * rsqrtf(qs) * invknorm;
                    float e = __expf(fmaf(beta, cosv, beta));
                    g_e[r] = e;
                    acc += e;
                }
            }

            if (!more) break;
            base = nxt;
            c0 = p0; c1 = p1; c2 = p2; c3 = p3;
        }
    }

    __shared__ float sm[256];
    sm[threadIdx.x] = acc;
    __syncthreads();
    for (int s = 128; s; s >>= 1) {
        if (threadIdx.x < s) sm[threadIdx.x] += sm[threadIdx.x + s];
        __syncthreads();
    }
    if (threadIdx.x == 0) g_part1[blockIdx.x] = sm[0];
}

// ---- block-wide deterministic sum of a partials array (same result in every block) ----
__device__ __forceinline__ float block_sum_partials(const float* __restrict__ part, int cnt,
                                                    float* __restrict__ sm /*256 floats*/) {
    float a = 0.f;
    for (int i = threadIdx.x; i < cnt; i += 256) a += part[i];
    sm[threadIdx.x] = a;
    __syncthreads();
    #pragma unroll
    for (int s = 128; s; s >>= 1) {
        if (threadIdx.x < s) sm[threadIdx.x] += sm[threadIdx.x + s];
        __syncthreads();
    }
    float r = sm[0];
    __syncthreads();
    return r;
}

// ---------------- kernel 2: interpolate + shift + sharpen, 4-wide ----------------
__global__ __launch_bounds__(256) void k_shift4(const float* __restrict__ wp, int n4, int n,
                                                int cnt1,
                                                const float* __restrict__ g_p,
                                                const float* __restrict__ s_p,
                                                const float* __restrict__ gamma_p) {
    __shared__ float sm[256];
    const float Se = block_sum_partials(g_part1, cnt1, sm);

    const float gg = *g_p;
    const float s0 = s_p[0], s1 = s_p[1], s2 = s_p[2];
    const float gamma = *gamma_p;
    const float one_m_g = 1.0f - gg;
    const float gs = gg / Se;

    float part = 0.f;
    int i = blockIdx.x * blockDim.x + threadIdx.x;
    if (i < n4) {
        int j = i << 2;
        int jm1 = (j == 0) ? (n - 1) : (j - 1);
        int jp4 = (j + 4 == n) ? 0 : (j + 4);

        float4 E  = reinterpret_cast<const float4*>(g_e)[i];
        float4 W  = reinterpret_cast<const float4*>(wp)[i];
        float em1 = g_e[jm1], ep4 = g_e[jp4];
        float wm1 = wp[jm1],  wp4 = wp[jp4];

        float a0 = fmaf(gs, em1, one_m_g * wm1);
        float a1 = fmaf(gs, E.x, one_m_g * W.x);
        float a2 = fmaf(gs, E.y, one_m_g * W.y);
        float a3 = fmaf(gs, E.z, one_m_g * W.z);
        float a4 = fmaf(gs, E.w, one_m_g * W.w);
        float a5 = fmaf(gs, ep4, one_m_g * wp4);

        float h0 = s0 * a0; h0 = fmaf(s1, a1, h0); h0 = fmaf(s2, a2, h0);
        float h1 = s0 * a1; h1 = fmaf(s1, a2, h1); h1 = fmaf(s2, a3, h1);
        float h2 = s0 * a2; h2 = fmaf(s1, a3, h2); h2 = fmaf(s2, a4, h2);
        float h3 = s0 * a3; h3 = fmaf(s1, a4, h3); h3 = fmaf(s2, a5, h3);

        float4 o;
        o.x = __powf(h0, gamma);
        o.y = __powf(h1, gamma);
        o.z = __powf(h2, gamma);
        o.w = __powf(h3, gamma);
        reinterpret_cast<float4*>(g_w)[i] = o;
        part = (o.x + o.y) + (o.z + o.w);
    }
    sm[threadIdx.x] = part;
    __syncthreads();
    for (int s = 128; s; s >>= 1) {
        if (threadIdx.x < s) sm[threadIdx.x] += sm[threadIdx.x + s];
        __syncthreads();
    }
    if (threadIdx.x == 0) g_part2[blockIdx.x] = sm[0];
}

// scalar fallback (n not divisible by 4)
__global__ __launch_bounds__(256) void k_shift1(const float* __restrict__ wp, int n,
                                                int cnt1,
                                                const float* __restrict__ g_p,
                                                const float* __restrict__ s_p,
                                                const float* __restrict__ gamma_p) {
    __shared__ float sm[256];
    const float Se = block_sum_partials(g_part1, cnt1, sm);

    const float gg = *g_p;
    const float s0 = s_p[0], s1 = s_p[1], s2 = s_p[2];
    const float gamma = *gamma_p;
    const float one_m_g = 1.0f - gg;
    const float gs = gg / Se;

    float part = 0.f;
    int tid = blockIdx.x * blockDim.x + threadIdx.x;
    int ntot = gridDim.x * blockDim.x;
    for (int i = tid; i < n; i += ntot) {
        int im1 = (i == 0) ? (n - 1) : (i - 1);
        int ip1 = (i == n - 1) ? 0 : (i + 1);
        float wgm = fmaf(gs, g_e[im1], one_m_g * wp[im1]);
        float wgc = fmaf(gs, g_e[i],   one_m_g * wp[i]);
        float wgp = fmaf(gs, g_e[ip1], one_m_g * wp[ip1]);
        float wh = s0 * wgm; wh = fmaf(s1, wgc, wh); wh = fmaf(s2, wgp, wh);
        float w = __powf(wh, gamma);
        g_w[i] = w;
        part += w;
    }
    sm[threadIdx.x] = part;
    __syncthreads();
    for (int s = 128; s; s >>= 1) {
        if (threadIdx.x < s) sm[threadIdx.x] += sm[threadIdx.x + s];
        __syncthreads();
    }
    if (threadIdx.x == 0) g_part2[blockIdx.x] = sm[0];
}

// ---------------- kernel 3: normalize ----------------
__global__ __launch_bounds__(256) void k_norm4(float4* __restrict__ out, int n4, int cnt2) {
    __shared__ float sm[256];
    const float Sw = block_sum_partials(g_part2, cnt2, sm);
    const float inv = 1.0f / (Sw + 1e-16f);

    int i = blockIdx.x * blockDim.x + threadIdx.x;
    if (i < n4) {
        float4 v = reinterpret_cast<const float4*>(g_w)[i];
        v.x *= inv; v.y *= inv; v.z *= inv; v.w *= inv;
        out[i] = v;
    }
}

__global__ __launch_bounds__(256) void k_norm1(float* __restrict__ out, int n, int cnt2) {
    __shared__ float sm[256];
    const float Sw = block_sum_partials(g_part2, cnt2, sm);
    const float inv = 1.0f / (Sw + 1e-16f);

    int i = blockIdx.x * blockDim.x + threadIdx.x;
    if (i < n) out[i] = g_w[i] * inv;
}

extern "C" void kernel_launch(void* const* d_in, const int* in_sizes, int n_in,
                              void* d_out, int out_size) {
    // inputs: mem [N,128], k [128], beta [1], g [1], s [3], gamma [1], w_prev [N]
    const float* mem    = (const float*)d_in[0];
    const float* k      = (const float*)d_in[1];
    const float* beta_p = (const float*)d_in[2];
    const float* g_p    = (const float*)d_in[3];
    const float* s_p    = (const float*)d_in[4];
    const float* gamma_p= (const float*)d_in[5];
    const float* wp     = (const float*)d_in[6];
    float* out = (float*)d_out;

    int n = in_sizes[6];  // N rows

    // one resident wave: 148 SMs * 4 blocks/SM (64 regs, 256 thr) = 592 blocks
    const int G1 = 592;

    k_sim<<<G1, 256>>>(mem, n, k, beta_p);

    if ((n & 3) == 0) {
        int n4 = n >> 2;
        int G3 = (n4 + 255) / 256;   // 1954 for n=2e6
        k_shift4<<<G3, 256>>>(wp, n4, n, G1, g_p, s_p, gamma_p);
        k_norm4<<<G3, 256>>>((float4*)out, n4, G3);
    } else {
        int G3 = 2048;
        k_shift1<<<G3, 256>>>(wp, n, G1, g_p, s_p, gamma_p);
        k_norm1<<<(n + 255) / 256, 256>>>(out, n, G3);
    }
}